// round 1
// baseline (speedup 1.0000x reference)
#include <cuda_runtime.h>
#include <math.h>

#define BSZ 2
#define LXX 2048
#define LYY 2048
#define DIM 1024
#define NH  16
#define DKK 64

// Scratch (allocation-free rule: __device__ globals)
__device__ float g_q[BSZ*NH*LXX*DKK];
__device__ float g_k[BSZ*NH*LYY*DKK];
__device__ float g_v[BSZ*NH*LYY*DKK];
__device__ float g_attn[BSZ*LXX*NH*DKK];

// ---------------------------------------------------------------------------
// GEMM: C(4096,1024) = A(4096,1024) @ W(1024,1024) + bias
// layout 0: plain row-major C[m*1024+n]
// layout 1: scatter to (b,h,x,dk): C[((b*NH+h)*LXX + x)*DKK + dk]
// 128x128 block tile, 8x8 per thread (2x2 quadrants of 4x4), BK=16.
// ---------------------------------------------------------------------------
__global__ void __launch_bounds__(256, 2)
gemm_kernel(const float* __restrict__ A, const float* __restrict__ W,
            const float* __restrict__ bias, float* __restrict__ C, int layout)
{
    __shared__ float As[16 * 132];   // transposed A tile: As[k][m], stride 132
    __shared__ float Bs[16 * 128];   // B tile: Bs[k][n]

    const int m0  = blockIdx.y * 128;
    const int n0  = blockIdx.x * 128;
    const int tid = threadIdx.x;
    const int ty  = tid >> 4;        // 0..15
    const int tx  = tid & 15;        // 0..15

    float acc[8][8];
    #pragma unroll
    for (int i = 0; i < 8; i++)
        #pragma unroll
        for (int j = 0; j < 8; j++) acc[i][j] = 0.0f;

    for (int k0 = 0; k0 < DIM; k0 += 16) {
        __syncthreads();
        // Load A tile 128x16, store transposed
        #pragma unroll
        for (int p = 0; p < 2; p++) {
            int s   = tid + p * 256;        // 0..511
            int row = s >> 2;               // 0..127
            int k4  = s & 3;                // 0..3
            float4 v = *(const float4*)(A + (size_t)(m0 + row) * DIM + k0 + k4 * 4);
            As[(k4*4 + 0) * 132 + row] = v.x;
            As[(k4*4 + 1) * 132 + row] = v.y;
            As[(k4*4 + 2) * 132 + row] = v.z;
            As[(k4*4 + 3) * 132 + row] = v.w;
        }
        // Load B tile 16x128
        #pragma unroll
        for (int p = 0; p < 2; p++) {
            int s  = tid + p * 256;         // 0..511
            int kr = s >> 5;                // 0..15
            int c4 = s & 31;                // 0..31
            *(float4*)(Bs + kr * 128 + c4 * 4) =
                *(const float4*)(W + (size_t)(k0 + kr) * 1024 + n0 + c4 * 4);
        }
        __syncthreads();

        #pragma unroll
        for (int d = 0; d < 16; d++) {
            float av[8], bv[8];
            float4 t0 = *(const float4*)(As + d * 132 + 4 * ty);
            float4 t1 = *(const float4*)(As + d * 132 + 64 + 4 * ty);
            av[0]=t0.x; av[1]=t0.y; av[2]=t0.z; av[3]=t0.w;
            av[4]=t1.x; av[5]=t1.y; av[6]=t1.z; av[7]=t1.w;
            float4 u0 = *(const float4*)(Bs + d * 128 + 4 * tx);
            float4 u1 = *(const float4*)(Bs + d * 128 + 64 + 4 * tx);
            bv[0]=u0.x; bv[1]=u0.y; bv[2]=u0.z; bv[3]=u0.w;
            bv[4]=u1.x; bv[5]=u1.y; bv[6]=u1.z; bv[7]=u1.w;
            #pragma unroll
            for (int i = 0; i < 8; i++)
                #pragma unroll
                for (int j = 0; j < 8; j++)
                    acc[i][j] = fmaf(av[i], bv[j], acc[i][j]);
        }
    }

    // Epilogue: add bias, write out (float4 per quadrant row)
    #pragma unroll
    for (int qi = 0; qi < 2; qi++) {
        #pragma unroll
        for (int ii = 0; ii < 4; ii++) {
            int m = m0 + qi * 64 + 4 * ty + ii;
            #pragma unroll
            for (int qj = 0; qj < 2; qj++) {
                int nb = n0 + qj * 64 + 4 * tx;
                float4 r;
                r.x = acc[qi*4 + ii][qj*4 + 0] + bias[nb + 0];
                r.y = acc[qi*4 + ii][qj*4 + 1] + bias[nb + 1];
                r.z = acc[qi*4 + ii][qj*4 + 2] + bias[nb + 2];
                r.w = acc[qi*4 + ii][qj*4 + 3] + bias[nb + 3];
                if (layout == 0) {
                    *(float4*)(C + (size_t)m * 1024 + nb) = r;
                } else {
                    int b  = m >> 11;       // m / 2048
                    int xr = m & 2047;
                    int hh = nb >> 6;       // nb / 64
                    int dk = nb & 63;
                    *(float4*)(C + (((size_t)(b * NH + hh)) * LXX + xr) * DKK + dk) = r;
                }
            }
        }
    }
}

// ---------------------------------------------------------------------------
// Flash attention: per (b,h), 64-query tile per block, 64-key tiles streamed.
// Smem tiles 64x64 fp32, XOR-swizzled at float4 granularity: phys_col4 =
// col4 ^ (row>>2). All inner LDS.128 conflict-free. P overwrites K tile.
// ---------------------------------------------------------------------------
__global__ void __launch_bounds__(256, 2)
attn_kernel(const float* __restrict__ mask)
{
    __shared__ float Qs [64 * 64];
    __shared__ float KPs[64 * 64];   // K tile, later reused for P
    __shared__ float Vs [64 * 64];

    const int bh = blockIdx.y;           // b*NH + h
    const int b  = bh >> 4;
    const int h  = bh & 15;
    const int x0 = blockIdx.x * 64;
    const int tid = threadIdx.x;
    const int ty  = tid >> 4;            // 0..15 (query row group)
    const int tx  = tid & 15;            // 0..15 (col group)

    const float* qp    = g_q + ((size_t)bh * LXX + x0) * DKK;
    const float* kp    = g_k + (size_t)bh * LYY * DKK;
    const float* vp    = g_v + (size_t)bh * LYY * DKK;
    const float* maskp = mask + ((size_t)b * LXX + x0) * LYY;

    // Load Q tile (swizzled)
    #pragma unroll
    for (int p = 0; p < 4; p++) {
        int s   = tid + p * 256;         // 0..1023
        int row = s >> 4;                // 0..63
        int d4  = s & 15;                // 0..15
        float4 v = *(const float4*)(qp + row * 64 + d4 * 4);
        *(float4*)(Qs + row * 64 + ((d4 ^ (row >> 2)) << 2)) = v;
    }

    float o[4][4];
    float m_r[4], l_r[4];
    #pragma unroll
    for (int ii = 0; ii < 4; ii++) {
        m_r[ii] = -INFINITY;
        l_r[ii] = 0.0f;
        #pragma unroll
        for (int c = 0; c < 4; c++) o[ii][c] = 0.0f;
    }

    for (int y0 = 0; y0 < LYY; y0 += 64) {
        __syncthreads();   // protect smem from previous iteration's readers
        // Load K, V tiles (swizzled)
        #pragma unroll
        for (int p = 0; p < 4; p++) {
            int s   = tid + p * 256;
            int row = s >> 4;
            int d4  = s & 15;
            int phys = ((d4 ^ (row >> 2)) << 2);
            float4 kv4 = *(const float4*)(kp + (y0 + row) * 64 + d4 * 4);
            *(float4*)(KPs + row * 64 + phys) = kv4;
            float4 vv4 = *(const float4*)(vp + (y0 + row) * 64 + d4 * 4);
            *(float4*)(Vs + row * 64 + phys) = vv4;
        }
        __syncthreads();

        // S = Q @ K^T   (reduction over d, vectorized in d4 chunks)
        float s_[4][4];
        #pragma unroll
        for (int ii = 0; ii < 4; ii++)
            #pragma unroll
            for (int jj = 0; jj < 4; jj++) s_[ii][jj] = 0.0f;

        #pragma unroll
        for (int d4 = 0; d4 < 16; d4++) {
            int qc = (d4 ^ ty) << 2;
            int kc = (d4 ^ tx) << 2;
            float4 qv[4], kv[4];
            #pragma unroll
            for (int ii = 0; ii < 4; ii++)
                qv[ii] = *(const float4*)(Qs + (4 * ty + ii) * 64 + qc);
            #pragma unroll
            for (int jj = 0; jj < 4; jj++)
                kv[jj] = *(const float4*)(KPs + (4 * tx + jj) * 64 + kc);
            #pragma unroll
            for (int ii = 0; ii < 4; ii++)
                #pragma unroll
                for (int jj = 0; jj < 4; jj++) {
                    s_[ii][jj] = fmaf(qv[ii].x, kv[jj].x, s_[ii][jj]);
                    s_[ii][jj] = fmaf(qv[ii].y, kv[jj].y, s_[ii][jj]);
                    s_[ii][jj] = fmaf(qv[ii].z, kv[jj].z, s_[ii][jj]);
                    s_[ii][jj] = fmaf(qv[ii].w, kv[jj].w, s_[ii][jj]);
                }
        }

        // scale + mask, row max
        float mx[4];
        #pragma unroll
        for (int ii = 0; ii < 4; ii++) {
            float4 mk = *(const float4*)(maskp + (size_t)(4 * ty + ii) * LYY + y0 + 4 * tx);
            s_[ii][0] = fmaf(s_[ii][0], 0.125f, mk.x);
            s_[ii][1] = fmaf(s_[ii][1], 0.125f, mk.y);
            s_[ii][2] = fmaf(s_[ii][2], 0.125f, mk.z);
            s_[ii][3] = fmaf(s_[ii][3], 0.125f, mk.w);
            mx[ii] = fmaxf(fmaxf(s_[ii][0], s_[ii][1]), fmaxf(s_[ii][2], s_[ii][3]));
        }
        #pragma unroll
        for (int off = 1; off < 16; off <<= 1)
            #pragma unroll
            for (int ii = 0; ii < 4; ii++)
                mx[ii] = fmaxf(mx[ii], __shfl_xor_sync(0xffffffffu, mx[ii], off));

        // online softmax update
        float alpha[4], rs[4];
        #pragma unroll
        for (int ii = 0; ii < 4; ii++) {
            float mn = fmaxf(m_r[ii], mx[ii]);
            alpha[ii] = __expf(m_r[ii] - mn);
            m_r[ii] = mn;
            #pragma unroll
            for (int jj = 0; jj < 4; jj++) s_[ii][jj] = __expf(s_[ii][jj] - mn);
            rs[ii] = (s_[ii][0] + s_[ii][1]) + (s_[ii][2] + s_[ii][3]);
        }
        #pragma unroll
        for (int off = 1; off < 16; off <<= 1)
            #pragma unroll
            for (int ii = 0; ii < 4; ii++)
                rs[ii] += __shfl_xor_sync(0xffffffffu, rs[ii], off);
        #pragma unroll
        for (int ii = 0; ii < 4; ii++) {
            l_r[ii] = l_r[ii] * alpha[ii] + rs[ii];
            #pragma unroll
            for (int c = 0; c < 4; c++) o[ii][c] *= alpha[ii];
        }

        __syncthreads();   // everyone done reading K tile
        // write P into KPs (swizzled)
        #pragma unroll
        for (int ii = 0; ii < 4; ii++) {
            float4 pr = make_float4(s_[ii][0], s_[ii][1], s_[ii][2], s_[ii][3]);
            *(float4*)(KPs + (4 * ty + ii) * 64 + ((tx ^ ty) << 2)) = pr;
        }
        __syncthreads();

        // O += P @ V  (reduction over j, vectorized in j4 chunks)
        #pragma unroll
        for (int j4 = 0; j4 < 16; j4++) {
            int pc = (j4 ^ ty) << 2;
            int vc = (tx ^ j4) << 2;
            float4 pv[4], vv[4];
            #pragma unroll
            for (int ii = 0; ii < 4; ii++)
                pv[ii] = *(const float4*)(KPs + (4 * ty + ii) * 64 + pc);
            #pragma unroll
            for (int jc = 0; jc < 4; jc++)
                vv[jc] = *(const float4*)(Vs + (4 * j4 + jc) * 64 + vc);
            #pragma unroll
            for (int ii = 0; ii < 4; ii++) {
                o[ii][0] = fmaf(pv[ii].x, vv[0].x, o[ii][0]);
                o[ii][0] = fmaf(pv[ii].y, vv[1].x, o[ii][0]);
                o[ii][0] = fmaf(pv[ii].z, vv[2].x, o[ii][0]);
                o[ii][0] = fmaf(pv[ii].w, vv[3].x, o[ii][0]);
                o[ii][1] = fmaf(pv[ii].x, vv[0].y, o[ii][1]);
                o[ii][1] = fmaf(pv[ii].y, vv[1].y, o[ii][1]);
                o[ii][1] = fmaf(pv[ii].z, vv[2].y, o[ii][1]);
                o[ii][1] = fmaf(pv[ii].w, vv[3].y, o[ii][1]);
                o[ii][2] = fmaf(pv[ii].x, vv[0].z, o[ii][2]);
                o[ii][2] = fmaf(pv[ii].y, vv[1].z, o[ii][2]);
                o[ii][2] = fmaf(pv[ii].z, vv[2].z, o[ii][2]);
                o[ii][2] = fmaf(pv[ii].w, vv[3].z, o[ii][2]);
                o[ii][3] = fmaf(pv[ii].x, vv[0].w, o[ii][3]);
                o[ii][3] = fmaf(pv[ii].y, vv[1].w, o[ii][3]);
                o[ii][3] = fmaf(pv[ii].z, vv[2].w, o[ii][3]);
                o[ii][3] = fmaf(pv[ii].w, vv[3].w, o[ii][3]);
            }
        }
    }

    // Epilogue: normalize, write to (b, x, h, dk) layout
    #pragma unroll
    for (int ii = 0; ii < 4; ii++) {
        float inv = 1.0f / l_r[ii];
        int xi = x0 + 4 * ty + ii;
        float4 r = make_float4(o[ii][0] * inv, o[ii][1] * inv,
                               o[ii][2] * inv, o[ii][3] * inv);
        *(float4*)(g_attn + (((size_t)b * LXX + xi) * NH + h) * DKK + 4 * tx) = r;
    }
}

// ---------------------------------------------------------------------------
extern "C" void kernel_launch(void* const* d_in, const int* in_sizes, int n_in,
                              void* d_out, int out_size)
{
    const float* x    = (const float*)d_in[0];
    const float* y    = (const float*)d_in[1];
    const float* mask = (const float*)d_in[2];
    const float* Wq   = (const float*)d_in[3];
    const float* bq   = (const float*)d_in[4];
    const float* Wk   = (const float*)d_in[5];
    const float* bk   = (const float*)d_in[6];
    const float* Wv   = (const float*)d_in[7];
    const float* bv   = (const float*)d_in[8];
    const float* Wo   = (const float*)d_in[9];
    const float* bo   = (const float*)d_in[10];
    float* out = (float*)d_out;

    float *qb, *kb, *vbuf, *abuf;
    cudaGetSymbolAddress((void**)&qb,   g_q);
    cudaGetSymbolAddress((void**)&kb,   g_k);
    cudaGetSymbolAddress((void**)&vbuf, g_v);
    cudaGetSymbolAddress((void**)&abuf, g_attn);

    dim3 ggrid(8, 32);   // N/128, M/128
    gemm_kernel<<<ggrid, 256>>>(x, Wq, bq, qb,   1);
    gemm_kernel<<<ggrid, 256>>>(y, Wk, bk, kb,   1);
    gemm_kernel<<<ggrid, 256>>>(y, Wv, bv, vbuf, 1);
    attn_kernel<<<dim3(32, 32), 256>>>(mask);
    gemm_kernel<<<ggrid, 256>>>(abuf, Wo, bo, out, 0);
}

// round 3
// speedup vs baseline: 2.2795x; 2.2795x over previous
#include <cuda_runtime.h>
#include <math.h>
#include <stdint.h>

#define BSZ 2
#define LXX 2048
#define LYY 2048
#define DIM 1024
#define NH  16
#define DKK 64

// Scratch (allocation-free rule: __device__ globals)
__device__ float g_q[BSZ*NH*LXX*DKK];
__device__ float g_k[BSZ*NH*LYY*DKK];
__device__ float g_v[BSZ*NH*LYY*DKK];
__device__ float g_attn[BSZ*LXX*NH*DKK];

// ---------------------------------------------------------------------------
__device__ __forceinline__ uint32_t f2tf32(float f) {
    uint32_t r; asm("cvt.rna.tf32.f32 %0, %1;" : "=r"(r) : "f"(f)); return r;
}
__device__ __forceinline__ void mma_tf32(float* d, const uint32_t* a,
                                         uint32_t b0, uint32_t b1) {
    asm volatile(
        "mma.sync.aligned.m16n8k8.row.col.f32.tf32.tf32.f32 "
        "{%0,%1,%2,%3}, {%4,%5,%6,%7}, {%8,%9}, {%0,%1,%2,%3};"
        : "+f"(d[0]), "+f"(d[1]), "+f"(d[2]), "+f"(d[3])
        : "r"(a[0]), "r"(a[1]), "r"(a[2]), "r"(a[3]), "r"(b0), "r"(b1));
}

// ---------------------------------------------------------------------------
// TF32 mma.sync GEMM: C(4096,1024) = A(4096,1024) @ W(1024,1024) + bias
// W used in native [K][N] row-major layout (mma B wants [k][n]).
// Block 128x128, BK=32. Warps 4m x 2n; warp tile 32x64 (2 mt x 8 nt).
// Smem pads: As stride 36 (frag bank = 4*r0+c0, unique),
//            Ws stride 136 (frag bank = 8*c0+r0, unique).
// layout 0: C[m*1024+n]; layout 1: scatter to (b,h,x,dk).
// ---------------------------------------------------------------------------
__global__ void __launch_bounds__(256, 2)
gemm_tc(const float* __restrict__ A, const float* __restrict__ W,
        const float* __restrict__ bias, float* __restrict__ C, int layout)
{
    __shared__ uint32_t As[128 * 36];
    __shared__ uint32_t Ws[32 * 136];
    __shared__ float    s_bias[128];

    const int tid  = threadIdx.x;
    const int lane = tid & 31;
    const int wid  = tid >> 5;
    const int wm   = wid & 3;        // 0..3 -> 32-row slab
    const int wn   = wid >> 2;       // 0..1 -> 64-col slab
    const int r0   = lane >> 2;      // 0..7
    const int c0   = lane & 3;       // 0..3
    const int m0   = blockIdx.y * 128;
    const int n0   = blockIdx.x * 128;

    if (tid < 128) s_bias[tid] = bias[n0 + tid];

    float acc[2][8][4];
    #pragma unroll
    for (int mt = 0; mt < 2; mt++)
        #pragma unroll
        for (int nt = 0; nt < 8; nt++)
            #pragma unroll
            for (int j = 0; j < 4; j++) acc[mt][nt][j] = 0.0f;

    for (int kt = 0; kt < 32; kt++) {
        // gmem -> regs
        float4 ra[4], rw[4];
        #pragma unroll
        for (int p = 0; p < 4; p++) {
            int s = tid + p * 256;                  // 0..1023
            int arow = s >> 3, ac4 = s & 7;
            ra[p] = *(const float4*)(A + (size_t)(m0 + arow) * DIM + kt * 32 + ac4 * 4);
            int wrow = s >> 5, wc4 = s & 31;
            rw[p] = *(const float4*)(W + (size_t)(kt * 32 + wrow) * 1024 + n0 + wc4 * 4);
        }
        __syncthreads();   // previous iter's frag reads done
        #pragma unroll
        for (int p = 0; p < 4; p++) {
            int s = tid + p * 256;
            int arow = s >> 3, ac4 = s & 7;
            uint4 ua = make_uint4(f2tf32(ra[p].x), f2tf32(ra[p].y),
                                  f2tf32(ra[p].z), f2tf32(ra[p].w));
            *(uint4*)(As + arow * 36 + ac4 * 4) = ua;
            int wrow = s >> 5, wc4 = s & 31;
            uint4 uw = make_uint4(f2tf32(rw[p].x), f2tf32(rw[p].y),
                                  f2tf32(rw[p].z), f2tf32(rw[p].w));
            *(uint4*)(Ws + wrow * 136 + wc4 * 4) = uw;
        }
        __syncthreads();

        #pragma unroll
        for (int k8 = 0; k8 < 4; k8++) {
            uint32_t a[2][4];
            #pragma unroll
            for (int mt = 0; mt < 2; mt++) {
                int rb = wm * 32 + mt * 16;
                a[mt][0] = As[(rb + r0)     * 36 + k8 * 8 + c0];
                a[mt][1] = As[(rb + r0 + 8) * 36 + k8 * 8 + c0];
                a[mt][2] = As[(rb + r0)     * 36 + k8 * 8 + c0 + 4];
                a[mt][3] = As[(rb + r0 + 8) * 36 + k8 * 8 + c0 + 4];
            }
            #pragma unroll
            for (int nt = 0; nt < 8; nt++) {
                int nb = wn * 64 + nt * 8 + r0;
                uint32_t b0 = Ws[(k8 * 8 + c0)     * 136 + nb];
                uint32_t b1 = Ws[(k8 * 8 + c0 + 4) * 136 + nb];
                mma_tf32(acc[0][nt], a[0], b0, b1);
                mma_tf32(acc[1][nt], a[1], b0, b1);
            }
        }
    }

    // Epilogue: bias + store (float2 per row-half)
    #pragma unroll
    for (int mt = 0; mt < 2; mt++) {
        #pragma unroll
        for (int nt = 0; nt < 8; nt++) {
            int nloc = wn * 64 + nt * 8 + 2 * c0;
            int n = n0 + nloc;
            float bx = s_bias[nloc], by = s_bias[nloc + 1];
            #pragma unroll
            for (int hh = 0; hh < 2; hh++) {
                int m = m0 + wm * 32 + mt * 16 + hh * 8 + r0;
                float2 v;
                v.x = acc[mt][nt][hh * 2 + 0] + bx;
                v.y = acc[mt][nt][hh * 2 + 1] + by;
                float* dst;
                if (layout == 0) {
                    dst = C + (size_t)m * 1024 + n;
                } else {
                    int b  = m >> 11, xr = m & 2047;
                    int hd = n >> 6,  dk = n & 63;
                    dst = C + (((size_t)(b * NH + hd)) * LXX + xr) * DKK + dk;
                }
                *(float2*)dst = v;
            }
        }
    }
}

// ---------------------------------------------------------------------------
// Flash attention with TF32 mma.sync.
// CTA: 256 thr (8 warps, 2m x 4n), 64-query tile, 64-key iterations.
// Dynamic smem (floats): Qs[64*68] @0, KPs[64*68] @4352 (K then P),
//                        Vs[64*72] @8704, RMX[64*4] @13312, RSM[64*4] @13568.
// All fragment LDS bank-conflict-free by pad choice (68: 4r+c; 72: 8k+n).
// ---------------------------------------------------------------------------
__global__ void __launch_bounds__(256, 2)
attn_kernel(const float* __restrict__ mask)
{
    extern __shared__ float sm[];
    uint32_t* Qs  = (uint32_t*)sm;            // stride 68
    uint32_t* KPs = (uint32_t*)(sm + 4352);   // stride 68
    uint32_t* Vs  = (uint32_t*)(sm + 8704);   // stride 72
    float*    RMX = sm + 13312;               // [64][4]
    float*    RSM = sm + 13568;               // [64][4]

    const int tid  = threadIdx.x;
    const int lane = tid & 31;
    const int wid  = tid >> 5;
    const int wm   = wid & 1;        // 0..1 -> 32-row slab
    const int wn   = wid >> 1;       // 0..3 -> 16-col slab
    const int r0   = lane >> 2;
    const int c0   = lane & 3;
    const int colb = wn * 16;

    const int bh = blockIdx.y, b = bh >> 4, h = bh & 15;
    const int x0 = blockIdx.x * 64;

    const float* qp    = g_q + ((size_t)bh * LXX + x0) * DKK;
    const float* kp    = g_k + (size_t)bh * LYY * DKK;
    const float* vp    = g_v + (size_t)bh * LYY * DKK;
    const float* maskp = mask + ((size_t)b * LXX + x0) * LYY;

    // Load Q once (tf32-rounded). Visibility covered by loop's syncthreads.
    #pragma unroll
    for (int p = 0; p < 4; p++) {
        int s = tid + p * 256;
        int row = s >> 4, c4 = s & 15;
        float4 v = *(const float4*)(qp + row * 64 + c4 * 4);
        uint4 u = make_uint4(f2tf32(v.x), f2tf32(v.y), f2tf32(v.z), f2tf32(v.w));
        *(uint4*)(Qs + row * 68 + c4 * 4) = u;
    }

    float o[2][2][4];
    float m_s[2][2], l_s[2][2];     // [mt][hh]
    #pragma unroll
    for (int mt = 0; mt < 2; mt++)
        #pragma unroll
        for (int hh = 0; hh < 2; hh++) {
            m_s[mt][hh] = -INFINITY; l_s[mt][hh] = 0.0f;
            o[mt][0][hh*2] = o[mt][0][hh*2+1] = 0.0f;
            o[mt][1][hh*2] = o[mt][1][hh*2+1] = 0.0f;
        }

    for (int y0 = 0; y0 < LYY; y0 += 64) {
        // gmem -> regs
        float4 kr[4], vr[4];
        #pragma unroll
        for (int p = 0; p < 4; p++) {
            int s = tid + p * 256;
            int row = s >> 4, c4 = s & 15;
            kr[p] = *(const float4*)(kp + (size_t)(y0 + row) * 64 + c4 * 4);
            vr[p] = *(const float4*)(vp + (size_t)(y0 + row) * 64 + c4 * 4);
        }
        __syncthreads();   // prev iter PV frag reads done
        #pragma unroll
        for (int p = 0; p < 4; p++) {
            int s = tid + p * 256;
            int row = s >> 4, c4 = s & 15;
            *(uint4*)(KPs + row * 68 + c4 * 4) =
                make_uint4(f2tf32(kr[p].x), f2tf32(kr[p].y), f2tf32(kr[p].z), f2tf32(kr[p].w));
            *(uint4*)(Vs + row * 72 + c4 * 4) =
                make_uint4(f2tf32(vr[p].x), f2tf32(vr[p].y), f2tf32(vr[p].z), f2tf32(vr[p].w));
        }
        __syncthreads();

        // ---- S = Q @ K^T ----
        float s_[2][2][4];
        #pragma unroll
        for (int mt = 0; mt < 2; mt++)
            #pragma unroll
            for (int nt = 0; nt < 2; nt++)
                #pragma unroll
                for (int j = 0; j < 4; j++) s_[mt][nt][j] = 0.0f;

        #pragma unroll
        for (int k8 = 0; k8 < 8; k8++) {
            uint32_t a[2][4];
            #pragma unroll
            for (int mt = 0; mt < 2; mt++) {
                int rb = wm * 32 + mt * 16;
                a[mt][0] = Qs[(rb + r0)     * 68 + k8 * 8 + c0];
                a[mt][1] = Qs[(rb + r0 + 8) * 68 + k8 * 8 + c0];
                a[mt][2] = Qs[(rb + r0)     * 68 + k8 * 8 + c0 + 4];
                a[mt][3] = Qs[(rb + r0 + 8) * 68 + k8 * 8 + c0 + 4];
            }
            #pragma unroll
            for (int nt = 0; nt < 2; nt++) {
                int key = colb + nt * 8 + r0;
                uint32_t b0 = KPs[key * 68 + k8 * 8 + c0];
                uint32_t b1 = KPs[key * 68 + k8 * 8 + c0 + 4];
                mma_tf32(s_[0][nt], a[0], b0, b1);
                mma_tf32(s_[1][nt], a[1], b0, b1);
            }
        }

        // ---- scale + mask + row max ----
        float mx[2][2];
        #pragma unroll
        for (int mt = 0; mt < 2; mt++) {
            #pragma unroll
            for (int hh = 0; hh < 2; hh++) {
                int row = wm * 32 + mt * 16 + hh * 8 + r0;
                float2 mk0 = *(const float2*)(maskp + (size_t)row * LYY + y0 + colb + 2 * c0);
                float2 mk1 = *(const float2*)(maskp + (size_t)row * LYY + y0 + colb + 8 + 2 * c0);
                s_[mt][0][hh*2+0] = fmaf(s_[mt][0][hh*2+0], 0.125f, mk0.x);
                s_[mt][0][hh*2+1] = fmaf(s_[mt][0][hh*2+1], 0.125f, mk0.y);
                s_[mt][1][hh*2+0] = fmaf(s_[mt][1][hh*2+0], 0.125f, mk1.x);
                s_[mt][1][hh*2+1] = fmaf(s_[mt][1][hh*2+1], 0.125f, mk1.y);
                mx[mt][hh] = fmaxf(fmaxf(s_[mt][0][hh*2], s_[mt][0][hh*2+1]),
                                   fmaxf(s_[mt][1][hh*2], s_[mt][1][hh*2+1]));
            }
        }
        #pragma unroll
        for (int off = 1; off <= 2; off <<= 1)
            #pragma unroll
            for (int mt = 0; mt < 2; mt++)
                #pragma unroll
                for (int hh = 0; hh < 2; hh++)
                    mx[mt][hh] = fmaxf(mx[mt][hh], __shfl_xor_sync(0xffffffffu, mx[mt][hh], off));
        if (c0 == 0) {
            #pragma unroll
            for (int mt = 0; mt < 2; mt++)
                #pragma unroll
                for (int hh = 0; hh < 2; hh++)
                    RMX[(wm * 32 + mt * 16 + hh * 8 + r0) * 4 + wn] = mx[mt][hh];
        }
        __syncthreads();   // also: all warps past S-mma -> KPs reusable for P

        float alpha[2][2];
        #pragma unroll
        for (int mt = 0; mt < 2; mt++) {
            #pragma unroll
            for (int hh = 0; hh < 2; hh++) {
                int row = wm * 32 + mt * 16 + hh * 8 + r0;
                float gm = fmaxf(fmaxf(RMX[row*4+0], RMX[row*4+1]),
                                 fmaxf(RMX[row*4+2], RMX[row*4+3]));
                float mn = fmaxf(m_s[mt][hh], gm);
                alpha[mt][hh] = __expf(m_s[mt][hh] - mn);
                m_s[mt][hh] = mn;
                // exp
                float rs = 0.0f;
                #pragma unroll
                for (int nt = 0; nt < 2; nt++) {
                    s_[mt][nt][hh*2+0] = __expf(s_[mt][nt][hh*2+0] - mn);
                    s_[mt][nt][hh*2+1] = __expf(s_[mt][nt][hh*2+1] - mn);
                    rs += s_[mt][nt][hh*2+0] + s_[mt][nt][hh*2+1];
                }
                #pragma unroll
                for (int off = 1; off <= 2; off <<= 1)
                    rs += __shfl_xor_sync(0xffffffffu, rs, off);
                if (c0 == 0) RSM[row * 4 + wn] = rs;
                // write P (tf32) into KPs
                #pragma unroll
                for (int nt = 0; nt < 2; nt++) {
                    uint2 pw = make_uint2(f2tf32(s_[mt][nt][hh*2+0]),
                                          f2tf32(s_[mt][nt][hh*2+1]));
                    *(uint2*)(KPs + row * 68 + colb + nt * 8 + 2 * c0) = pw;
                }
            }
        }
        __syncthreads();   // P + RSM visible

        // l update + O rescale
        #pragma unroll
        for (int mt = 0; mt < 2; mt++) {
            #pragma unroll
            for (int hh = 0; hh < 2; hh++) {
                int row = wm * 32 + mt * 16 + hh * 8 + r0;
                float ls = RSM[row*4+0] + RSM[row*4+1] + RSM[row*4+2] + RSM[row*4+3];
                l_s[mt][hh] = l_s[mt][hh] * alpha[mt][hh] + ls;
                o[mt][0][hh*2+0] *= alpha[mt][hh];
                o[mt][0][hh*2+1] *= alpha[mt][hh];
                o[mt][1][hh*2+0] *= alpha[mt][hh];
                o[mt][1][hh*2+1] *= alpha[mt][hh];
            }
        }

        // ---- O += P @ V ----
        #pragma unroll
        for (int k8 = 0; k8 < 8; k8++) {
            uint32_t a[2][4];
            #pragma unroll
            for (int mt = 0; mt < 2; mt++) {
                int rb = wm * 32 + mt * 16;
                a[mt][0] = KPs[(rb + r0)     * 68 + k8 * 8 + c0];
                a[mt][1] = KPs[(rb + r0 + 8) * 68 + k8 * 8 + c0];
                a[mt][2] = KPs[(rb + r0)     * 68 + k8 * 8 + c0 + 4];
                a[mt][3] = KPs[(rb + r0 + 8) * 68 + k8 * 8 + c0 + 4];
            }
            #pragma unroll
            for (int nt = 0; nt < 2; nt++) {
                int nb = colb + nt * 8 + r0;
                uint32_t b0 = Vs[(k8 * 8 + c0)     * 72 + nb];
                uint32_t b1 = Vs[(k8 * 8 + c0 + 4) * 72 + nb];
                mma_tf32(o[0][nt], a[0], b0, b1);
                mma_tf32(o[1][nt], a[1], b0, b1);
            }
        }
    }

    // Epilogue: normalize, store to g_attn[b][x][h][dk]
    #pragma unroll
    for (int mt = 0; mt < 2; mt++) {
        #pragma unroll
        for (int hh = 0; hh < 2; hh++) {
            int xr = x0 + wm * 32 + mt * 16 + hh * 8 + r0;
            float inv = 1.0f / l_s[mt][hh];
            #pragma unroll
            for (int nt = 0; nt < 2; nt++) {
                int dk = colb + nt * 8 + 2 * c0;
                float2 v = make_float2(o[mt][nt][hh*2+0] * inv,
                                       o[mt][nt][hh*2+1] * inv);
                *(float2*)(g_attn + (((size_t)b * LXX + xr) * NH + h) * DKK + dk) = v;
            }
        }
    }
}

// ---------------------------------------------------------------------------
extern "C" void kernel_launch(void* const* d_in, const int* in_sizes, int n_in,
                              void* d_out, int out_size)
{
    const float* x    = (const float*)d_in[0];
    const float* y    = (const float*)d_in[1];
    const float* mask = (const float*)d_in[2];
    const float* Wq   = (const float*)d_in[3];
    const float* bq   = (const float*)d_in[4];
    const float* Wk   = (const float*)d_in[5];
    const float* bk   = (const float*)d_in[6];
    const float* Wv   = (const float*)d_in[7];
    const float* bv   = (const float*)d_in[8];
    const float* Wo   = (const float*)d_in[9];
    const float* bo   = (const float*)d_in[10];
    float* out = (float*)d_out;

    float *qb, *kb, *vbuf, *abuf;
    cudaGetSymbolAddress((void**)&qb,   g_q);
    cudaGetSymbolAddress((void**)&kb,   g_k);
    cudaGetSymbolAddress((void**)&vbuf, g_v);
    cudaGetSymbolAddress((void**)&abuf, g_attn);

    static int smem_set = 0;
    if (!smem_set) {
        cudaFuncSetAttribute(attn_kernel,
                             cudaFuncAttributeMaxDynamicSharedMemorySize, 55296);
        smem_set = 1;
    }

    dim3 ggrid(8, 32);   // N/128, M/128
    gemm_tc<<<ggrid, 256>>>(x,    Wq, bq, qb,   1);
    gemm_tc<<<ggrid, 256>>>(y,    Wk, bk, kb,   1);
    gemm_tc<<<ggrid, 256>>>(y,    Wv, bv, vbuf, 1);
    attn_kernel<<<dim3(32, 32), 256, 55296>>>(mask);
    gemm_tc<<<ggrid, 256>>>(abuf, Wo, bo, out,  0);
}

// round 4
// speedup vs baseline: 2.8278x; 1.2405x over previous
#include <cuda_runtime.h>
#include <math.h>
#include <stdint.h>

#define BSZ 2
#define LXX 2048
#define LYY 2048
#define DIM 1024
#define NH  16
#define DKK 64

// Scratch (allocation-free rule: __device__ globals)
__device__ float g_q[BSZ*NH*LXX*DKK];
__device__ float g_k[BSZ*NH*LYY*DKK];
__device__ float g_v[BSZ*NH*LYY*DKK];
__device__ float g_attn[BSZ*LXX*NH*DKK];

// ---------------------------------------------------------------------------
__device__ __forceinline__ uint32_t f2tf32(float f) {
    uint32_t r; asm("cvt.rna.tf32.f32 %0, %1;" : "=r"(r) : "f"(f)); return r;
}
__device__ __forceinline__ void mma_tf32(float* d, const uint32_t* a,
                                         uint32_t b0, uint32_t b1) {
    asm volatile(
        "mma.sync.aligned.m16n8k8.row.col.f32.tf32.tf32.f32 "
        "{%0,%1,%2,%3}, {%4,%5,%6,%7}, {%8,%9}, {%0,%1,%2,%3};"
        : "+f"(d[0]), "+f"(d[1]), "+f"(d[2]), "+f"(d[3])
        : "r"(a[0]), "r"(a[1]), "r"(a[2]), "r"(a[3]), "r"(b0), "r"(b1));
}
__device__ __forceinline__ uint32_t s2u(const void* p) {
    uint32_t a;
    asm("{ .reg .u64 t; cvta.to.shared.u64 t, %1; cvt.u32.u64 %0, t; }"
        : "=r"(a) : "l"(p));
    return a;
}
__device__ __forceinline__ void cpa16(uint32_t d, const float* s) {
    asm volatile("cp.async.cg.shared.global [%0], [%1], 16;" :: "r"(d), "l"(s));
}
__device__ __forceinline__ void cpa_commit() {
    asm volatile("cp.async.commit_group;" ::: "memory");
}
__device__ __forceinline__ void cpa_wait1() {
    asm volatile("cp.async.wait_group 1;" ::: "memory");
}
__device__ __forceinline__ void cpa_wait0() {
    asm volatile("cp.async.wait_group 0;" ::: "memory");
}

// ---------------------------------------------------------------------------
// TF32 mma.sync GEMM (as Round 3, epilogue optionally rounds output to tf32).
// C(4096,1024) = A(4096,1024) @ W(1024,1024) + bias
// layout 0: C[m*1024+n] fp32; layout 1: scatter (b,h,x,dk), tf32-rounded.
// ---------------------------------------------------------------------------
__global__ void __launch_bounds__(256, 2)
gemm_tc(const float* __restrict__ A, const float* __restrict__ W,
        const float* __restrict__ bias, float* __restrict__ C, int layout)
{
    __shared__ uint32_t As[128 * 36];
    __shared__ uint32_t Ws[32 * 136];
    __shared__ float    s_bias[128];

    const int tid  = threadIdx.x;
    const int lane = tid & 31;
    const int wid  = tid >> 5;
    const int wm   = wid & 3;
    const int wn   = wid >> 2;
    const int r0   = lane >> 2;
    const int c0   = lane & 3;
    const int m0   = blockIdx.y * 128;
    const int n0   = blockIdx.x * 128;

    if (tid < 128) s_bias[tid] = bias[n0 + tid];

    float acc[2][8][4];
    #pragma unroll
    for (int mt = 0; mt < 2; mt++)
        #pragma unroll
        for (int nt = 0; nt < 8; nt++)
            #pragma unroll
            for (int j = 0; j < 4; j++) acc[mt][nt][j] = 0.0f;

    for (int kt = 0; kt < 32; kt++) {
        float4 ra[4], rw[4];
        #pragma unroll
        for (int p = 0; p < 4; p++) {
            int s = tid + p * 256;
            int arow = s >> 3, ac4 = s & 7;
            ra[p] = *(const float4*)(A + (size_t)(m0 + arow) * DIM + kt * 32 + ac4 * 4);
            int wrow = s >> 5, wc4 = s & 31;
            rw[p] = *(const float4*)(W + (size_t)(kt * 32 + wrow) * 1024 + n0 + wc4 * 4);
        }
        __syncthreads();
        #pragma unroll
        for (int p = 0; p < 4; p++) {
            int s = tid + p * 256;
            int arow = s >> 3, ac4 = s & 7;
            *(uint4*)(As + arow * 36 + ac4 * 4) =
                make_uint4(f2tf32(ra[p].x), f2tf32(ra[p].y), f2tf32(ra[p].z), f2tf32(ra[p].w));
            int wrow = s >> 5, wc4 = s & 31;
            *(uint4*)(Ws + wrow * 136 + wc4 * 4) =
                make_uint4(f2tf32(rw[p].x), f2tf32(rw[p].y), f2tf32(rw[p].z), f2tf32(rw[p].w));
        }
        __syncthreads();

        #pragma unroll
        for (int k8 = 0; k8 < 4; k8++) {
            uint32_t a[2][4];
            #pragma unroll
            for (int mt = 0; mt < 2; mt++) {
                int rb = wm * 32 + mt * 16;
                a[mt][0] = As[(rb + r0)     * 36 + k8 * 8 + c0];
                a[mt][1] = As[(rb + r0 + 8) * 36 + k8 * 8 + c0];
                a[mt][2] = As[(rb + r0)     * 36 + k8 * 8 + c0 + 4];
                a[mt][3] = As[(rb + r0 + 8) * 36 + k8 * 8 + c0 + 4];
            }
            #pragma unroll
            for (int nt = 0; nt < 8; nt++) {
                int nb = wn * 64 + nt * 8 + r0;
                uint32_t b0 = Ws[(k8 * 8 + c0)     * 136 + nb];
                uint32_t b1 = Ws[(k8 * 8 + c0 + 4) * 136 + nb];
                mma_tf32(acc[0][nt], a[0], b0, b1);
                mma_tf32(acc[1][nt], a[1], b0, b1);
            }
        }
    }

    #pragma unroll
    for (int mt = 0; mt < 2; mt++) {
        #pragma unroll
        for (int nt = 0; nt < 8; nt++) {
            int nloc = wn * 64 + nt * 8 + 2 * c0;
            int n = n0 + nloc;
            float bx = s_bias[nloc], by = s_bias[nloc + 1];
            #pragma unroll
            for (int hh = 0; hh < 2; hh++) {
                int m = m0 + wm * 32 + mt * 16 + hh * 8 + r0;
                float vx = acc[mt][nt][hh * 2 + 0] + bx;
                float vy = acc[mt][nt][hh * 2 + 1] + by;
                float2 v;
                float* dst;
                if (layout == 0) {
                    v = make_float2(vx, vy);
                    dst = C + (size_t)m * 1024 + n;
                } else {
                    // pre-round to tf32 for the attention kernel
                    v = make_float2(__uint_as_float(f2tf32(vx)),
                                    __uint_as_float(f2tf32(vy)));
                    int b  = m >> 11, xr = m & 2047;
                    int hd = n >> 6,  dk = n & 63;
                    dst = C + (((size_t)(b * NH + hd)) * LXX + xr) * DKK + dk;
                }
                *(float2*)dst = v;
            }
        }
    }
}

// ---------------------------------------------------------------------------
// Flash attention v2.
// CTA = 128 threads (4 warps), q-tile 128 (warp owns 32 rows, mt=2, full key
// range), k-tile 64 with cp.async double buffering.
// Q fragments register-resident for all 32 key-tiles. Softmax fully
// intra-warp. P->A-frag conversion intra-warp via private smem slice.
// Smem (floats): Qs[128*68]@0 (reused as Pbuf), K0@8704, K1@13056,
//                V0@17408, V1@22016 (stride 72). Total 26624 f = 106496 B.
// All fragment LDS conflict-free via pads (68: bank 4r+c; 72: 8c+r).
// ---------------------------------------------------------------------------
__global__ void __launch_bounds__(128)
attn_kernel(const float* __restrict__ mask)
{
    extern __shared__ float sm[];
    const uint32_t base = s2u(sm);
    const uint32_t qa  = base;
    const uint32_t ka0 = base + 8704u  * 4u;
    const uint32_t ka1 = base + 13056u * 4u;
    const uint32_t va0 = base + 17408u * 4u;
    const uint32_t va1 = base + 22016u * 4u;

    const uint32_t* Qu = (const uint32_t*)sm;
    float*          Pf = sm;                       // Pbuf aliases Qs

    const int tid  = threadIdx.x;
    const int lane = tid & 31;
    const int w    = tid >> 5;        // warp 0..3 -> 32-row slab
    const int r0   = lane >> 2;
    const int c0   = lane & 3;
    const int wrow = w * 32;

    const int bh = blockIdx.y, b = bh >> 4, h = bh & 15;
    const int x0 = blockIdx.x * 128;

    const float* qp    = g_q + ((size_t)bh * LXX + x0) * DKK;
    const float* kp    = g_k + (size_t)bh * LYY * DKK;
    const float* vp    = g_v + (size_t)bh * LYY * DKK;
    const float* maskp = mask + ((size_t)b * LXX + x0) * LYY;

    // ---- prologue: async copies ----
    // Q tile 128x64 -> Qs (stride 68)
    #pragma unroll
    for (int p = 0; p < 16; p++) {
        int id = tid + p * 128;
        int row = id >> 4, c4 = id & 15;
        cpa16(qa + (uint32_t)(row * 68 + c4 * 4) * 4u, qp + row * 64 + c4 * 4);
    }
    // K0/V0
    #pragma unroll
    for (int p = 0; p < 8; p++) {
        int id = tid + p * 128;
        int row = id >> 4, c4 = id & 15;
        cpa16(ka0 + (uint32_t)(row * 68 + c4 * 4) * 4u, kp + row * 64 + c4 * 4);
        cpa16(va0 + (uint32_t)(row * 72 + c4 * 4) * 4u, vp + row * 64 + c4 * 4);
    }
    cpa_commit();
    // K1/V1
    #pragma unroll
    for (int p = 0; p < 8; p++) {
        int id = tid + p * 128;
        int row = id >> 4, c4 = id & 15;
        cpa16(ka1 + (uint32_t)(row * 68 + c4 * 4) * 4u, kp + 4096 + row * 64 + c4 * 4);
        cpa16(va1 + (uint32_t)(row * 72 + c4 * 4) * 4u, vp + 4096 + row * 64 + c4 * 4);
    }
    cpa_commit();
    cpa_wait1();          // Q,K0,V0 ready
    __syncthreads();

    // ---- Q fragments into registers (held across all iterations) ----
    uint32_t aq[2][8][4];
    #pragma unroll
    for (int mt = 0; mt < 2; mt++)
        #pragma unroll
        for (int k8 = 0; k8 < 8; k8++) {
            int rb = wrow + mt * 16;
            aq[mt][k8][0] = Qu[(rb + r0)     * 68 + k8 * 8 + c0];
            aq[mt][k8][1] = Qu[(rb + r0 + 8) * 68 + k8 * 8 + c0];
            aq[mt][k8][2] = Qu[(rb + r0)     * 68 + k8 * 8 + c0 + 4];
            aq[mt][k8][3] = Qu[(rb + r0 + 8) * 68 + k8 * 8 + c0 + 4];
        }
    __syncthreads();   // all warps done reading Qs before anyone writes P

    float o[2][8][4];
    float m_s[2][2], l_s[2][2];
    #pragma unroll
    for (int mt = 0; mt < 2; mt++) {
        #pragma unroll
        for (int hh = 0; hh < 2; hh++) { m_s[mt][hh] = -INFINITY; l_s[mt][hh] = 0.0f; }
        #pragma unroll
        for (int nt = 0; nt < 8; nt++)
            #pragma unroll
            for (int j = 0; j < 4; j++) o[mt][nt][j] = 0.0f;
    }

    for (int i = 0; i < 32; i++) {
        const int y0 = i * 64;
        const uint32_t* Ku = (const uint32_t*)(sm + ((i & 1) ? 13056 : 8704));
        const uint32_t* Vu = (const uint32_t*)(sm + ((i & 1) ? 22016 : 17408));

        // ---- S = Q @ K^T ----
        float s_[2][8][4];
        #pragma unroll
        for (int mt = 0; mt < 2; mt++)
            #pragma unroll
            for (int nt = 0; nt < 8; nt++)
                #pragma unroll
                for (int j = 0; j < 4; j++) s_[mt][nt][j] = 0.0f;

        #pragma unroll
        for (int k8 = 0; k8 < 8; k8++) {
            #pragma unroll
            for (int nt = 0; nt < 8; nt++) {
                uint32_t b0 = Ku[(nt * 8 + r0) * 68 + k8 * 8 + c0];
                uint32_t b1 = Ku[(nt * 8 + r0) * 68 + k8 * 8 + c0 + 4];
                mma_tf32(s_[0][nt], aq[0][k8], b0, b1);
                mma_tf32(s_[1][nt], aq[1][k8], b0, b1);
            }
        }

        // ---- scale + mask ----
        #pragma unroll
        for (int mt = 0; mt < 2; mt++)
            #pragma unroll
            for (int hh = 0; hh < 2; hh++) {
                const float* mrow = maskp + (size_t)(wrow + mt * 16 + hh * 8 + r0) * LYY + y0;
                #pragma unroll
                for (int nt = 0; nt < 8; nt++) {
                    float2 mk = *(const float2*)(mrow + nt * 8 + 2 * c0);
                    s_[mt][nt][hh*2+0] = fmaf(s_[mt][nt][hh*2+0], 0.125f, mk.x);
                    s_[mt][nt][hh*2+1] = fmaf(s_[mt][nt][hh*2+1], 0.125f, mk.y);
                }
            }

        // ---- intra-warp online softmax ----
        float alpha[2][2];
        #pragma unroll
        for (int mt = 0; mt < 2; mt++)
            #pragma unroll
            for (int hh = 0; hh < 2; hh++) {
                float mx = -INFINITY;
                #pragma unroll
                for (int nt = 0; nt < 8; nt++)
                    mx = fmaxf(mx, fmaxf(s_[mt][nt][hh*2], s_[mt][nt][hh*2+1]));
                mx = fmaxf(mx, __shfl_xor_sync(0xffffffffu, mx, 1));
                mx = fmaxf(mx, __shfl_xor_sync(0xffffffffu, mx, 2));
                float mn = fmaxf(m_s[mt][hh], mx);
                alpha[mt][hh] = __expf(m_s[mt][hh] - mn);
                m_s[mt][hh] = mn;
                float rs = 0.0f;
                #pragma unroll
                for (int nt = 0; nt < 8; nt++) {
                    s_[mt][nt][hh*2+0] = __expf(s_[mt][nt][hh*2+0] - mn);
                    s_[mt][nt][hh*2+1] = __expf(s_[mt][nt][hh*2+1] - mn);
                    rs += s_[mt][nt][hh*2+0] + s_[mt][nt][hh*2+1];
                }
                rs += __shfl_xor_sync(0xffffffffu, rs, 1);
                rs += __shfl_xor_sync(0xffffffffu, rs, 2);
                l_s[mt][hh] = l_s[mt][hh] * alpha[mt][hh] + rs;
                #pragma unroll
                for (int nt = 0; nt < 8; nt++) {
                    o[mt][nt][hh*2+0] *= alpha[mt][hh];
                    o[mt][nt][hh*2+1] *= alpha[mt][hh];
                }
            }

        // ---- P -> A fragments (intra-warp, via private Pbuf slice) ----
        #pragma unroll
        for (int mt = 0; mt < 2; mt++) {
            int rb = wrow + mt * 16;
            #pragma unroll
            for (int nt = 0; nt < 8; nt++) {
                *(float2*)(Pf + (rb + r0) * 68 + nt * 8 + 2 * c0) =
                    make_float2(__uint_as_float(f2tf32(s_[mt][nt][0])),
                                __uint_as_float(f2tf32(s_[mt][nt][1])));
                *(float2*)(Pf + (rb + r0 + 8) * 68 + nt * 8 + 2 * c0) =
                    make_float2(__uint_as_float(f2tf32(s_[mt][nt][2])),
                                __uint_as_float(f2tf32(s_[mt][nt][3])));
            }
        }
        __syncwarp();
        uint32_t pa[2][8][4];
        #pragma unroll
        for (int mt = 0; mt < 2; mt++) {
            int rb = wrow + mt * 16;
            #pragma unroll
            for (int k8 = 0; k8 < 8; k8++) {
                pa[mt][k8][0] = Qu[(rb + r0)     * 68 + k8 * 8 + c0];
                pa[mt][k8][1] = Qu[(rb + r0 + 8) * 68 + k8 * 8 + c0];
                pa[mt][k8][2] = Qu[(rb + r0)     * 68 + k8 * 8 + c0 + 4];
                pa[mt][k8][3] = Qu[(rb + r0 + 8) * 68 + k8 * 8 + c0 + 4];
            }
        }

        // ---- O += P @ V ----
        #pragma unroll
        for (int k8 = 0; k8 < 8; k8++) {
            #pragma unroll
            for (int nt = 0; nt < 8; nt++) {
                uint32_t b0 = Vu[(k8 * 8 + c0)     * 72 + nt * 8 + r0];
                uint32_t b1 = Vu[(k8 * 8 + c0 + 4) * 72 + nt * 8 + r0];
                mma_tf32(o[0][nt], pa[0][k8], b0, b1);
                mma_tf32(o[1][nt], pa[1][k8], b0, b1);
            }
        }

        // ---- pipeline: prefetch tile i+2 into buffer (i&1) ----
        __syncthreads();   // all warps done reading K/V buf (i&1) ... (for i+2)
        if (i + 2 < 32) {
            const uint32_t kd = (i & 1) ? ka1 : ka0;
            const uint32_t vd = (i & 1) ? va1 : va0;
            const float* ks = kp + (size_t)(i + 2) * 4096;
            const float* vs = vp + (size_t)(i + 2) * 4096;
            #pragma unroll
            for (int p = 0; p < 8; p++) {
                int id = tid + p * 128;
                int row = id >> 4, c4 = id & 15;
                cpa16(kd + (uint32_t)(row * 68 + c4 * 4) * 4u, ks + row * 64 + c4 * 4);
                cpa16(vd + (uint32_t)(row * 72 + c4 * 4) * 4u, vs + row * 64 + c4 * 4);
            }
            cpa_commit();
            cpa_wait1();    // tile i+1 complete
        } else {
            cpa_wait0();
        }
        __syncthreads();    // copies visible to all warps
    }

    // ---- epilogue: normalize, tf32-round, store (b,x,h,dk) ----
    #pragma unroll
    for (int mt = 0; mt < 2; mt++)
        #pragma unroll
        for (int hh = 0; hh < 2; hh++) {
            int xr = x0 + wrow + mt * 16 + hh * 8 + r0;
            float inv = 1.0f / l_s[mt][hh];
            float* drow = g_attn + (((size_t)b * LXX + xr) * NH + h) * DKK;
            #pragma unroll
            for (int nt = 0; nt < 8; nt++) {
                float2 v = make_float2(
                    __uint_as_float(f2tf32(o[mt][nt][hh*2+0] * inv)),
                    __uint_as_float(f2tf32(o[mt][nt][hh*2+1] * inv)));
                *(float2*)(drow + nt * 8 + 2 * c0) = v;
            }
        }
}

// ---------------------------------------------------------------------------
extern "C" void kernel_launch(void* const* d_in, const int* in_sizes, int n_in,
                              void* d_out, int out_size)
{
    const float* x    = (const float*)d_in[0];
    const float* y    = (const float*)d_in[1];
    const float* mask = (const float*)d_in[2];
    const float* Wq   = (const float*)d_in[3];
    const float* bq   = (const float*)d_in[4];
    const float* Wk   = (const float*)d_in[5];
    const float* bk   = (const float*)d_in[6];
    const float* Wv   = (const float*)d_in[7];
    const float* bv   = (const float*)d_in[8];
    const float* Wo   = (const float*)d_in[9];
    const float* bo   = (const float*)d_in[10];
    float* out = (float*)d_out;

    float *qb, *kb, *vbuf, *abuf;
    cudaGetSymbolAddress((void**)&qb,   g_q);
    cudaGetSymbolAddress((void**)&kb,   g_k);
    cudaGetSymbolAddress((void**)&vbuf, g_v);
    cudaGetSymbolAddress((void**)&abuf, g_attn);

    static int smem_set = 0;
    if (!smem_set) {
        cudaFuncSetAttribute(attn_kernel,
                             cudaFuncAttributeMaxDynamicSharedMemorySize, 106496);
        smem_set = 1;
    }

    dim3 ggrid(8, 32);   // N/128, M/128
    gemm_tc<<<ggrid, 256>>>(x,    Wq, bq, qb,   1);
    gemm_tc<<<ggrid, 256>>>(y,    Wk, bk, kb,   1);
    gemm_tc<<<ggrid, 256>>>(y,    Wv, bv, vbuf, 1);
    attn_kernel<<<dim3(16, 32), 128, 106496>>>(mask);
    gemm_tc<<<ggrid, 256>>>(abuf, Wo, bo, out,  0);
}